// round 17
// baseline (speedup 1.0000x reference)
#include <cuda_runtime.h>
#include <cuda_fp16.h>
#include <cstdint>

// Problem constants (E=8, R=64, B=4, S=4096, D=2048)
#define E_N   8
#define RNK   64
#define DIM   2048
#define NTOK  16384
#define TM    128
#define NTHR  512

// ---------------- helpers ----------------
__device__ __forceinline__ uint32_t smem_u32(const void* p) {
    uint32_t a;
    asm("{ .reg .u64 t; cvta.to.shared.u64 t, %1; cvt.u32.u64 %0, t; }" : "=r"(a) : "l"(p));
    return a;
}
__device__ __forceinline__ uint32_t swz(uint32_t o) { return o ^ ((o >> 3) & 0x70); }

// pack two fp32 -> fp16x2 (a -> low half, b -> high half)
__device__ __forceinline__ uint32_t pk2(float a, float b) {
    uint32_t r;
    asm("cvt.rn.f16x2.f32 %0, %1, %2;" : "=r"(r) : "f"(b), "f"(a));
    return r;
}

__device__ __forceinline__ void ldm_x4(uint32_t a, uint32_t r[4]) {
    asm volatile("ldmatrix.sync.aligned.m8n8.x4.shared.b16 {%0,%1,%2,%3}, [%4];"
                 : "=r"(r[0]), "=r"(r[1]), "=r"(r[2]), "=r"(r[3]) : "r"(a));
}
__device__ __forceinline__ void mma16816(float* c, const uint32_t* a, const uint32_t* b) {
    asm volatile("mma.sync.aligned.m16n8k16.row.col.f32.f16.f16.f32 "
                 "{%0,%1,%2,%3}, {%4,%5,%6,%7}, {%8,%9}, {%0,%1,%2,%3};"
                 : "+f"(c[0]), "+f"(c[1]), "+f"(c[2]), "+f"(c[3])
                 : "r"(a[0]), "r"(a[1]), "r"(a[2]), "r"(a[3]), "r"(b[0]), "r"(b[1]));
}

// ---------------- SMEM layout (bytes) ----------------
// 64    : tok[128] (512B, ends 576)
// 640   : scan[18] (72B)
// 1024  : X bufs fp16 (128 rows x 128B, swz) 16K x4; X0..X3 (end 66560)
//         stage2 B bufs reuse X region: 16K x4 @ same slots
// 66560 : A bufs fp16 8K x4 (end 99328)
// 99328 : H fp16 16K (end 115712)
#define SM_TOK    64
#define SM_SCAN   640
#define SM_X0     1024
#define X_STRIDE  16384
#define SM_B0     1024
#define B_STRIDE  16384
#define SM_A0     66560
#define A_STRIDE  8192
#define SM_H      99328
#define SMEM_BYTES 115712

// ---------------- main kernel (sort fused as prologue) ----------------
__global__ void __launch_bounds__(NTHR, 1)
k_main(const float* __restrict__ x,
       const float* __restrict__ Aw,
       const float* __restrict__ Bw,
       const int* __restrict__ ti,
       float* __restrict__ out) {
    const int e = blockIdx.y;
    const int mstart = blockIdx.x * TM;

    extern __shared__ char smc[];
    const uint32_t sbu = smem_u32(smc);
    const int tid = threadIdx.x;
    const int wid = tid >> 5;
    const int lane = tid & 31;
    const int g = lane >> 2;
    const int tq = lane & 3;
    // stage-1 warp tile: m16 x n32
    const int s1mg = wid >> 1;
    const int s1ng = wid & 1;
    // stage-2 warp tile: m32 x n32
    const int s2mg = wid >> 2;
    const int s2ng = wid & 3;
    int* tok = (int*)(smc + SM_TOK);
    int* scan = (int*)(smc + SM_SCAN);

    // ===== fused sort prologue: compute this CTA's 128 token IDs =====
    {
        if (tid < TM) tok[tid] = -1;
        const int4* tv = (const int4*)ti + tid * 8;   // 32 tokens per thread
        int c = 0;
#pragma unroll
        for (int i = 0; i < 8; ++i) {
            int4 w = tv[i];
            c += (w.x == e) + (w.y == e) + (w.z == e) + (w.w == e);
        }
        // warp inclusive scan of c
        int pre = c;
#pragma unroll
        for (int d = 1; d < 32; d <<= 1) {
            int y = __shfl_up_sync(0xffffffffu, pre, d);
            if (lane >= d) pre += y;
        }
        if (lane == 31) scan[wid] = pre;
        __syncthreads();
        if (wid == 0) {
            int v = (lane < 16) ? scan[lane] : 0;
            int wpre = v;
#pragma unroll
            for (int d = 1; d < 16; d <<= 1) {
                int y = __shfl_up_sync(0xffffffffu, wpre, d);
                if (lane >= d) wpre += y;
            }
            if (lane < 16) scan[lane] = wpre - v;   // exclusive warp offsets
            if (lane == 15) scan[16] = wpre;        // total count for expert e
        }
        __syncthreads();
        const int cnt = scan[16];
        if (mstart >= cnt) return;                  // uniform across CTA
        int r = scan[wid] + (pre - c);              // this thread's first rank
        const int rend = mstart + TM;
        if (r < rend && r + c > mstart) {
#pragma unroll
            for (int i = 0; i < 8; ++i) {
                int4 w = tv[i];
                int tbase = tid * 32 + i * 4;
#pragma unroll
                for (int j = 0; j < 4; ++j) {
                    int v = (j == 0) ? w.x : (j == 1) ? w.y : (j == 2) ? w.z : w.w;
                    if (v == e) {
                        if (r >= mstart && r < rend) tok[r - mstart] = tbase + j;
                        ++r;
                    }
                }
            }
        }
        __syncthreads();
    }

    const float* Arow = Aw + (size_t)e * RNK * DIM;
    const float* Brow = Bw + (size_t)e * DIM * RNK;

    // ldmatrix lane patterns (pre-swizzle, relative to tile row base)
    const uint32_t bpair = (uint32_t)((lane & 7) + ((lane >> 4) << 3)) * 128 +
                           (uint32_t)((lane >> 3) & 1) * 16;          // 16-row n-pair
    const uint32_t apat  = (uint32_t)(lane & 15) * 128 + (uint32_t)(lane >> 4) * 16; // m16 A-op

    // ---- fill mappings (coalesced full 128B lines per LDG instr) ----
    const int xfr = tid >> 3, xfq = tid & 7;
    const int xt0 = tok[xfr], xt1 = tok[xfr + 64];
    const float* xp0 = x + (size_t)(xt0 < 0 ? 0 : xt0) * DIM;
    const float* xp1 = x + (size_t)(xt1 < 0 ? 0 : xt1) * DIM;
    float4 vx[4];
    const int fr = tid >> 3, fq = tid & 7;
    float4 va[2];

#define LOAD_X(K0)                                                              \
    do {                                                                        \
        float4 z = make_float4(0.f, 0.f, 0.f, 0.f);                             \
        vx[0] = (xt0 >= 0) ? *(const float4*)(xp0 + (K0) + xfq * 4) : z;        \
        vx[1] = (xt0 >= 0) ? *(const float4*)(xp0 + (K0) + 32 + xfq * 4) : z;   \
        vx[2] = (xt1 >= 0) ? *(const float4*)(xp1 + (K0) + xfq * 4) : z;        \
        vx[3] = (xt1 >= 0) ? *(const float4*)(xp1 + (K0) + 32 + xfq * 4) : z;   \
    } while (0)

#define STORE_X(BUF)                                                            \
    do {                                                                        \
        char* xb_ = smc + SM_X0 + (BUF) * X_STRIDE;                             \
        *(uint2*)(xb_ + swz((uint32_t)xfr * 128 + xfq * 8)) =                   \
            make_uint2(pk2(vx[0].x, vx[0].y), pk2(vx[0].z, vx[0].w));           \
        *(uint2*)(xb_ + swz((uint32_t)xfr * 128 + 64 + xfq * 8)) =              \
            make_uint2(pk2(vx[1].x, vx[1].y), pk2(vx[1].z, vx[1].w));           \
        *(uint2*)(xb_ + swz((uint32_t)(xfr + 64) * 128 + xfq * 8)) =            \
            make_uint2(pk2(vx[2].x, vx[2].y), pk2(vx[2].z, vx[2].w));           \
        *(uint2*)(xb_ + swz((uint32_t)(xfr + 64) * 128 + 64 + xfq * 8)) =       \
            make_uint2(pk2(vx[3].x, vx[3].y), pk2(vx[3].z, vx[3].w));           \
    } while (0)

#define LOAD_A(K0)                                                              \
    do {                                                                        \
        _Pragma("unroll") for (int i = 0; i < 2; ++i) va[i] =                   \
            *(const float4*)(Arow + (size_t)fr * DIM + (K0) + fq * 4 + i * 32); \
    } while (0)

#define STORE_A(BUF)                                                            \
    do {                                                                        \
        char* ah = smc + SM_A0 + (BUF) * A_STRIDE;                              \
        _Pragma("unroll") for (int i = 0; i < 2; ++i) {                         \
            uint32_t p0 = pk2(va[i].x, va[i].y);                                \
            uint32_t p1 = pk2(va[i].z, va[i].w);                                \
            uint32_t off = swz((uint32_t)fr * 128 + fq * 8 + i * 64);           \
            *(uint2*)(ah + off) = make_uint2(p0, p1);                           \
        }                                                                       \
    } while (0)

    // ===== stage 1: H[128,64] = X[128,2048] * A_e^T =====
    float acc1[4][4];
#pragma unroll
    for (int j = 0; j < 4; ++j)
#pragma unroll
        for (int q = 0; q < 4; ++q) acc1[j][q] = 0.f;

    // prologue: fill bufs 0,1; regs hold chunk 2
    LOAD_X(0);
    LOAD_A(0);
    STORE_X(0);
    STORE_A(0);
    LOAD_X(64);
    LOAD_A(64);
    STORE_X(1);
    STORE_A(1);
    LOAD_X(128);
    LOAD_A(128);
    __syncthreads();

    for (int c = 0; c < 32; ++c) {
        const uint32_t xbB = sbu + SM_X0 + (uint32_t)(c & 3) * X_STRIDE;
        const uint32_t ahB = sbu + SM_A0 + (uint32_t)(c & 3) * A_STRIDE;
#pragma unroll
        for (int kk = 0; kk < 4; ++kk) {
            uint32_t xf[4], bh[2][4];
            uint32_t xo = swz((uint32_t)(s1mg * 16) * 128 + apat + kk * 32);
            ldm_x4(xbB + xo, xf);
            uint32_t ao0 = swz((uint32_t)(s1ng * 32) * 128 + bpair + kk * 32);
            uint32_t ao1 = swz((uint32_t)(s1ng * 32 + 16) * 128 + bpair + kk * 32);
            ldm_x4(ahB + ao0, bh[0]);
            ldm_x4(ahB + ao1, bh[1]);
#pragma unroll
            for (int jj = 0; jj < 2; ++jj) {
                mma16816(acc1[jj * 2], xf, bh[jj]);
                mma16816(acc1[jj * 2 + 1], xf, bh[jj] + 2);
            }
        }
        if (c < 30) {
            STORE_X((c + 2) & 3);
            STORE_A((c + 2) & 3);
        }
        if (c < 29) {
            LOAD_X((c + 3) * 64);
            LOAD_A((c + 3) * 64);
        }
        if (c & 1) __syncthreads();
    }

    // ===== stage 2 fills (B): 128n x 64r fp32 per chunk =====
    // Rows PERMUTED within each 16-block: n16 -> (n16&1)*8 + (n16>>1) so the two
    // n8 MMA tiles interleave -> epilogue writes 4 contiguous n per thread.
    const int bfn = tid >> 3, bfq = tid & 7;
    float4 vb[4];

#define LOAD_B(N0)                                                              \
    do {                                                                        \
        const float* s0 = Brow + (size_t)((N0) + bfn) * RNK + bfq * 4;          \
        const float* s1 = Brow + (size_t)((N0) + bfn + 64) * RNK + bfq * 4;     \
        vb[0] = *(const float4*)(s0);                                           \
        vb[1] = *(const float4*)(s0 + 32);                                      \
        vb[2] = *(const float4*)(s1);                                           \
        vb[3] = *(const float4*)(s1 + 32);                                      \
    } while (0)

#define STORE_B(BUF)                                                            \
    do {                                                                        \
        char* bh_ = smc + SM_B0 + (BUF) * B_STRIDE;                             \
        _Pragma("unroll") for (int i = 0; i < 4; ++i) {                         \
            uint32_t p0 = pk2(vb[i].x, vb[i].y);                                \
            uint32_t p1 = pk2(vb[i].z, vb[i].w);                                \
            uint32_t r_ = (uint32_t)bfn + (i >> 1) * 64;                        \
            uint32_t n16_ = r_ & 15u;                                           \
            uint32_t rs_ = (r_ & ~15u) + ((n16_ & 1u) << 3) + (n16_ >> 1);      \
            uint32_t off = swz(rs_ * 128 + bfq * 8 + (i & 1) * 64);             \
            *(uint2*)(bh_ + off) = make_uint2(p0, p1);                          \
        }                                                                       \
    } while (0)

    LOAD_B(0);   // start GMEM reads early (X region safe: synced after c=31)

    // ===== H -> SMEM fp16 (fragment-consistent layout) =====
    {
        char* hh = smc + SM_H;
#pragma unroll
        for (int j = 0; j < 4; ++j) {
            int col = s1ng * 32 + j * 8 + 2 * tq;
            int r0 = s1mg * 16 + g;
            uint32_t p0 = pk2(acc1[j][0], acc1[j][1]);
            *(uint32_t*)(hh + swz((uint32_t)r0 * 128 + (uint32_t)col * 2)) = p0;
            uint32_t p1 = pk2(acc1[j][2], acc1[j][3]);
            *(uint32_t*)(hh + swz((uint32_t)(r0 + 8) * 128 + (uint32_t)col * 2)) = p1;
        }
    }
    STORE_B(0);
    LOAD_B(128);
    STORE_B(1);
    LOAD_B(256);
    __syncthreads();

    // preload ALL H fragments into registers (reused across all 16 n-chunks)
    uint32_t hf[2][4][4];
#pragma unroll
    for (int mt = 0; mt < 2; ++mt)
#pragma unroll
        for (int kk = 0; kk < 4; ++kk) {
            uint32_t ho = swz((uint32_t)(s2mg * 32 + mt * 16) * 128 + apat + kk * 32);
            ldm_x4(sbu + SM_H + ho, hf[mt][kk]);
        }

    // stage-2 output tokens for this warp
    int tko[2][2];
#pragma unroll
    for (int mt = 0; mt < 2; ++mt) {
        tko[mt][0] = tok[s2mg * 32 + mt * 16 + g];
        tko[mt][1] = tok[s2mg * 32 + mt * 16 + 8 + g];
    }

    // ===== stage 2: O[128,2048] = H[128,64] * B_e^T, 16 n-chunks of 128 =====
    for (int nc = 0; nc < 16; ++nc) {
        float acc2[2][4][4];
#pragma unroll
        for (int mt = 0; mt < 2; ++mt)
#pragma unroll
            for (int j = 0; j < 4; ++j)
#pragma unroll
                for (int q = 0; q < 4; ++q) acc2[mt][j][q] = 0.f;

        const uint32_t bbB = sbu + SM_B0 + (uint32_t)(nc & 3) * B_STRIDE;
#pragma unroll
        for (int kk = 0; kk < 4; ++kk) {
            uint32_t bh[2][4];
            uint32_t bo0 = swz((uint32_t)(s2ng * 32) * 128 + bpair + kk * 32);
            uint32_t bo1 = swz((uint32_t)(s2ng * 32 + 16) * 128 + bpair + kk * 32);
            ldm_x4(bbB + bo0, bh[0]);
            ldm_x4(bbB + bo1, bh[1]);
#pragma unroll
            for (int jj = 0; jj < 2; ++jj)
#pragma unroll
                for (int mt = 0; mt < 2; ++mt) {
                    mma16816(acc2[mt][jj * 2], hf[mt][kk], bh[jj]);
                    mma16816(acc2[mt][jj * 2 + 1], hf[mt][kk], bh[jj] + 2);
                }
        }

        // epilogue: STG.128 evict-first, 4 contiguous cols per thread
        const int nb0 = nc * 128 + s2ng * 32 + 4 * tq;
#pragma unroll
        for (int mt = 0; mt < 2; ++mt)
#pragma unroll
            for (int jj = 0; jj < 2; ++jj) {
                int colo = nb0 + jj * 16;
                float* t0 = acc2[mt][jj * 2];
                float* t1 = acc2[mt][jj * 2 + 1];
                if (tko[mt][0] >= 0)
                    __stcs((float4*)(out + (size_t)tko[mt][0] * DIM + colo),
                           make_float4(t0[0], t1[0], t0[1], t1[1]));
                if (tko[mt][1] >= 0)
                    __stcs((float4*)(out + (size_t)tko[mt][1] * DIM + colo),
                           make_float4(t0[2], t1[2], t0[3], t1[3]));
            }

        if (nc < 14) STORE_B((nc + 2) & 3);
        if (nc < 13) LOAD_B((nc + 3) * 128);
        if (nc & 1) __syncthreads();
    }
}

// ---------------- launch ----------------
extern "C" void kernel_launch(void* const* d_in, const int* in_sizes, int n_in,
                              void* d_out, int out_size) {
    const float* x  = (const float*)d_in[0];   // [B,S,D]
    const float* Aw = (const float*)d_in[1];   // [E,R,D]
    const float* Bw = (const float*)d_in[2];   // [E,D,R]
    const int*   ti = (const int*)d_in[3];     // [B,S]
    float* out = (float*)d_out;
    (void)in_sizes; (void)n_in; (void)out_size;

    static int smem_set = 0;
    if (!smem_set) {
        cudaFuncSetAttribute(k_main, cudaFuncAttributeMaxDynamicSharedMemorySize, SMEM_BYTES);
        smem_set = 1;
    }

    dim3 grid(NTOK / TM, E_N, 1);
    k_main<<<grid, NTHR, SMEM_BYTES>>>(x, Aw, Bw, ti, out);
}